// round 12
// baseline (speedup 1.0000x reference)
#include <cuda_runtime.h>
#include <math.h>

#define BB 8
#define CC 256
#define TT 16
#define HWN 1024
#define CR 16

// ---------------- scratch (device globals; no allocation) -------------------
__device__ float g_sp[BB * CC * HWN];   // spatial pooled mean  [b, c, hw]
__device__ float g_tp[BB * CC * TT];    // temporal pooled mean [b, c, t]
__device__ float g_cp[BB * CC];         // channel pooled mean  [b, c]
__device__ float g_comb[BB * CC * TT];  // temporal_att * channel_att
__device__ float g_att[BB * CC * HWN];  // spatial attention    [b, c, hw]

__device__ __forceinline__ float sigmoidf(float a) {
    return 1.0f / (1.0f + __expf(-a));
}

// ---------------- K1: pooling (measured 27.5us, 63.9% DRAM) ------------------
__global__ void __launch_bounds__(256) pool_kernel(const float* __restrict__ x) {
    const int bc  = blockIdx.x;
    const int tid = threadIdx.x;
    const float4* xb = (const float4*)(x + (size_t)bc * (TT * HWN));

    float4 sp = make_float4(0.f, 0.f, 0.f, 0.f);
    float tpar[TT];

#pragma unroll
    for (int t = 0; t < TT; t++) {
        float4 v = xb[t * (HWN / 4) + tid];
        sp.x += v.x; sp.y += v.y; sp.z += v.z; sp.w += v.w;
        tpar[t] = (v.x + v.y) + (v.z + v.w);
    }

    float4 spo;
    spo.x = sp.x * (1.f / TT); spo.y = sp.y * (1.f / TT);
    spo.z = sp.z * (1.f / TT); spo.w = sp.w * (1.f / TT);
    ((float4*)(g_sp + (size_t)bc * HWN))[tid] = spo;

    __shared__ float wsum[8][TT];
    const int lane = tid & 31;
    const int wid  = tid >> 5;
#pragma unroll
    for (int t = 0; t < TT; t++) {
        float s = tpar[t];
#pragma unroll
        for (int off = 16; off > 0; off >>= 1)
            s += __shfl_down_sync(0xffffffffu, s, off);
        if (lane == 0) wsum[wid][t] = s;
    }
    __syncthreads();
    if (tid < TT) {
        float s = 0.f;
#pragma unroll
        for (int w = 0; w < 8; w++) s += wsum[w][tid];
        g_tp[bc * TT + tid] = s * (1.f / HWN);
        wsum[0][tid] = s;
    }
    __syncthreads();
    if (tid == 0) {
        float tot = 0.f;
#pragma unroll
        for (int t = 0; t < TT; t++) tot += wsum[0][t];
        g_cp[bc] = tot * (1.f / (TT * HWN));
    }
}

// ---------------- K2: middle — spatial att (bid<1024) + small SE -------------
// grid = 1152, 256 threads, 33KB dyn smem (w-buffer overlaid w1 -> w2).
// att block = (b, 8-hw window); thread = (c-group of 8 channels, hw lane).
#define ATT_SMEM_FLOATS (4096 + 4096 + 128)   // wbuf + stage + hidf

__global__ void __launch_bounds__(256) attmid_kernel(
        const float* __restrict__ ws1, const float* __restrict__ bs1,
        const float* __restrict__ ws2, const float* __restrict__ bs2,
        const float* __restrict__ wt1, const float* __restrict__ bt1,
        const float* __restrict__ wt2, const float* __restrict__ bt2,
        const float* __restrict__ wc1, const float* __restrict__ bc1,
        const float* __restrict__ wc2, const float* __restrict__ bc2) {
    extern __shared__ float sm[];
    const int tid = threadIdx.x;

    if (blockIdx.x < 1024) {
        float* wbuf  = sm;           // [r][c]=4096 (w1), later [c][r]=4096 (w2)
        float* stage = sm + 4096;    // [c8][r][hwl] 4096
        float* hidf  = sm + 8192;    // [r][hwl] 128

        const int b   = blockIdx.x >> 7;
        const int hw0 = (blockIdx.x & 127) * 8;
        const int c8  = tid >> 3;    // 0..31 -> channels c8*8..c8*8+7
        const int hwl = tid & 7;     // 0..7

        for (int i = tid; i < CR * CC; i += 256) wbuf[i] = ws1[i];
        __syncthreads();

        // phase 1: 8 upfront g_sp loads, then 16 rows x 2 LDS.128 + 8 FMA
        const float* spb = g_sp + (size_t)(b * CC) * HWN + hw0 + hwl;
        float v0 = spb[(size_t)(c8 * 8 + 0) * HWN];
        float v1 = spb[(size_t)(c8 * 8 + 1) * HWN];
        float v2 = spb[(size_t)(c8 * 8 + 2) * HWN];
        float v3 = spb[(size_t)(c8 * 8 + 3) * HWN];
        float v4 = spb[(size_t)(c8 * 8 + 4) * HWN];
        float v5 = spb[(size_t)(c8 * 8 + 5) * HWN];
        float v6 = spb[(size_t)(c8 * 8 + 6) * HWN];
        float v7 = spb[(size_t)(c8 * 8 + 7) * HWN];

#pragma unroll
        for (int r = 0; r < CR; r++) {
            const float4 wa = *(const float4*)&wbuf[r * CC + c8 * 8];
            const float4 wb = *(const float4*)&wbuf[r * CC + c8 * 8 + 4];
            float s;
            s = wa.x * v0;
            s = fmaf(wa.y, v1, s);
            s = fmaf(wa.z, v2, s);
            s = fmaf(wa.w, v3, s);
            s = fmaf(wb.x, v4, s);
            s = fmaf(wb.y, v5, s);
            s = fmaf(wb.z, v6, s);
            s = fmaf(wb.w, v7, s);
            stage[(c8 * CR + r) * 8 + hwl] = s;
        }
        __syncthreads();

        // phase 2: reduce 32 partials + bias + ReLU (128 threads);
        // meanwhile all threads also stage w2 into wbuf (w1 no longer needed).
        if (tid < CR * 8) {
            const int r  = tid >> 3;
            const int hl = tid & 7;
            float s = __ldg(&bs1[r]);
#pragma unroll
            for (int g = 0; g < 32; g++) s += stage[(g * CR + r) * 8 + hl];
            hidf[r * 8 + hl] = fmaxf(s, 0.f);
        }
        for (int i = tid; i < CC * CR; i += 256) wbuf[i] = ws2[i];
        __syncthreads();

        // phase 3: att for this thread's 8 channels (w2 via LDS.128)
        float hv[CR];
#pragma unroll
        for (int r = 0; r < CR; r++) hv[r] = hidf[r * 8 + hwl];

        float* attb = g_att + (size_t)(b * CC) * HWN + hw0 + hwl;
#pragma unroll
        for (int i = 0; i < 8; i++) {
            const int c = c8 * 8 + i;
            const float4* wr = (const float4*)&wbuf[c * CR];
            float a = __ldg(&bs2[c]);
            const float4 w0 = wr[0];
            a = fmaf(w0.x, hv[0], a);  a = fmaf(w0.y, hv[1], a);
            a = fmaf(w0.z, hv[2], a);  a = fmaf(w0.w, hv[3], a);
            const float4 w1 = wr[1];
            a = fmaf(w1.x, hv[4], a);  a = fmaf(w1.y, hv[5], a);
            a = fmaf(w1.z, hv[6], a);  a = fmaf(w1.w, hv[7], a);
            const float4 w2 = wr[2];
            a = fmaf(w2.x, hv[8],  a); a = fmaf(w2.y, hv[9],  a);
            a = fmaf(w2.z, hv[10], a); a = fmaf(w2.w, hv[11], a);
            const float4 w3 = wr[3];
            a = fmaf(w3.x, hv[12], a); a = fmaf(w3.y, hv[13], a);
            a = fmaf(w3.z, hv[14], a); a = fmaf(w3.w, hv[15], a);
            attb[(size_t)c * HWN] = sigmoidf(a);
        }
    } else {
        // ---- temporal + channel SE -> g_comb (proven design) ----
        const int idx = blockIdx.x - 1024;   // 0..127
        const int b   = idx >> 4;
        const int t   = idx & 15;

        float* pt   = sm;          // [256]
        float* pc   = sm + 256;    // [256]
        float* hids = sm + 512;    // [32]

        pt[tid] = g_tp[(b * CC + tid) * TT + t];
        pc[tid] = g_cp[b * CC + tid];
        __syncthreads();

        if (tid < CR) {
            float s = bt1[tid];
            for (int c = 0; c < CC; c++) s = fmaf(wt1[tid * CC + c], pt[c], s);
            hids[tid] = fmaxf(s, 0.f);
        } else if (tid < 2 * CR) {
            const int r = tid - CR;
            float s = bc1[r];
            for (int c = 0; c < CC; c++) s = fmaf(wc1[r * CC + c], pc[c], s);
            hids[tid] = fmaxf(s, 0.f);
        }
        __syncthreads();

        float at = bt2[tid];
        float ac = bc2[tid];
#pragma unroll
        for (int r = 0; r < CR; r++) {
            at = fmaf(wt2[tid * CR + r], hids[r],      at);
            ac = fmaf(wc2[tid * CR + r], hids[CR + r], ac);
        }
        g_comb[(b * CC + tid) * TT + t] = sigmoidf(at) * sigmoidf(ac);
    }
}

// ---------------- K3: pure streaming apply (measured 38.4us, 74% DRAM) -------
__global__ void __launch_bounds__(256) apply_kernel(const float* __restrict__ x,
                                                    float* __restrict__ out) {
    const int bc  = blockIdx.x;
    const int tid = threadIdx.x;

    __shared__ float combs[TT];
    if (tid < TT) combs[tid] = g_comb[bc * TT + tid];

    const float4 a = ((const float4*)(g_att + (size_t)bc * HWN))[tid];
    __syncthreads();

    const float4* xp = (const float4*)(x + (size_t)bc * (TT * HWN));
    float4* op       = (float4*)(out + (size_t)bc * (TT * HWN));

#pragma unroll
    for (int t = 0; t < TT; t++) {
        const float s = combs[t];
        float4 v = xp[t * (HWN / 4) + tid];
        v.x = v.x * a.x * s;
        v.y = v.y * a.y * s;
        v.z = v.z * a.z * s;
        v.w = v.w * a.w * s;
        op[t * (HWN / 4) + tid] = v;
    }
}

// ---------------- launch -----------------------------------------------------
extern "C" void kernel_launch(void* const* d_in, const int* in_sizes, int n_in,
                              void* d_out, int out_size) {
    const float* x   = (const float*)d_in[0];
    const float* ws1 = (const float*)d_in[1];
    const float* bs1 = (const float*)d_in[2];
    const float* ws2 = (const float*)d_in[3];
    const float* bs2 = (const float*)d_in[4];
    const float* wt1 = (const float*)d_in[5];
    const float* bt1 = (const float*)d_in[6];
    const float* wt2 = (const float*)d_in[7];
    const float* bt2 = (const float*)d_in[8];
    const float* wc1 = (const float*)d_in[9];
    const float* bc1 = (const float*)d_in[10];
    const float* wc2 = (const float*)d_in[11];
    const float* bc2 = (const float*)d_in[12];
    float* out = (float*)d_out;

    pool_kernel<<<BB * CC, 256>>>(x);
    attmid_kernel<<<1152, 256, ATT_SMEM_FLOATS * sizeof(float)>>>(
        ws1, bs1, ws2, bs2, wt1, bt1, wt2, bt2, wc1, bc1, wc2, bc2);
    apply_kernel<<<BB * CC, 256>>>(x, out);
}

// round 15
// speedup vs baseline: 1.0598x; 1.0598x over previous
#include <cuda_runtime.h>
#include <math.h>

#define BB 8
#define CC 256
#define TT 16
#define HWN 1024
#define CR 16
#define G 1024   // persistent grid; 7 CTAs/SM * 148 = 1036 >= 1024 (co-resident)

// ---------------- scratch (device globals; no allocation) -------------------
__device__ float g_hid_part[4 * BB * CR * HWN];  // partial hidden [q][b][r][hw] (2MB)
__device__ float g_tpp[BB * TT * 32 * CC];       // tp partials [b][t][tile][c] (4MB)
__device__ float g_cpp[BB * 32 * CC];            // cp partials [b][tile][c] (256KB)
__device__ float g_comb[BB * CC * TT];           // temporal_att * channel_att
__device__ float g_att[BB * CC * HWN];           // spatial attention (8MB)
__device__ unsigned g_barcnt;                    // barrier arrival counter
__device__ unsigned g_bargen;                    // barrier generation

__device__ __forceinline__ float sigmoidf(float a) {
    return 1.0f / (1.0f + __expf(-a));
}

// all-CTA barrier; safe because all G CTAs are co-resident.
__device__ __forceinline__ void grid_barrier() {
    __syncthreads();
    if (threadIdx.x == 0) {
        volatile unsigned* genp = &g_bargen;
        const unsigned gen = *genp;          // read BEFORE arrival
        __threadfence();                     // publish this CTA's writes
        const unsigned a = atomicAdd(&g_barcnt, 1u);
        if (a == (unsigned)(G - 1)) {
            atomicExch(&g_barcnt, 0u);
            __threadfence();
            atomicAdd(&g_bargen, 1u);        // release
        } else {
            while (*genp == gen) { __nanosleep(64); }
        }
        __threadfence();                     // acquire
    }
    __syncthreads();
}

// ---------------- fused persistent kernel ------------------------------------
__global__ void __launch_bounds__(256, 7) fused_kernel(
        const float* __restrict__ x,
        const float* __restrict__ ws1, const float* __restrict__ bs1,
        const float* __restrict__ ws2, const float* __restrict__ bs2,
        const float* __restrict__ wt1, const float* __restrict__ bt1,
        const float* __restrict__ wt2, const float* __restrict__ bt2,
        const float* __restrict__ wc1, const float* __restrict__ bc1,
        const float* __restrict__ wc2, const float* __restrict__ bc2,
        float* __restrict__ out) {
    __shared__ float sm[4096];   // 16 KB, reused per phase
    const int tid = threadIdx.x;
    const int bid = blockIdx.x;

    // ===== Phase A: one (b, tile, q) job per CTA =============================
    {
        float* w1s  = sm;            // [r][c_local]   1024
        float* sp_s = sm + 1024;     // [c_local][hw]  2048
        float* tp_s = sm + 3072;     // [t][c_local]   1024

        const int q    = bid & 3;
        const int tile = (bid >> 2) & 31;
        const int b    = bid >> 7;

        for (int i = tid; i < CR * 64; i += 256)
            w1s[i] = ws1[(i >> 6) * CC + q * 64 + (i & 63)];

        const int f4  = tid & 7;
        const int cl2 = tid >> 3;
        const float4* xb = (const float4*)x;

#pragma unroll
        for (int i = 0; i < 2; i++) {
            const int c_local = cl2 + 32 * i;
            const int c = q * 64 + c_local;
            const size_t rowbase = (size_t)(b * CC + c) * TT * (HWN / 4) + tile * 8 + f4;
            float4 sp = make_float4(0.f, 0.f, 0.f, 0.f);
#pragma unroll
            for (int t = 0; t < TT; t++) {
                float4 v = xb[rowbase + t * (HWN / 4)];
                sp.x += v.x; sp.y += v.y; sp.z += v.z; sp.w += v.w;
                float s = (v.x + v.y) + (v.z + v.w);
                s += __shfl_down_sync(0xffffffffu, s, 4, 8);
                s += __shfl_down_sync(0xffffffffu, s, 2, 8);
                s += __shfl_down_sync(0xffffffffu, s, 1, 8);
                if (f4 == 0) tp_s[t * 64 + c_local] = s;
            }
            float4 spo;
            spo.x = sp.x * (1.f / TT); spo.y = sp.y * (1.f / TT);
            spo.z = sp.z * (1.f / TT); spo.w = sp.w * (1.f / TT);
            ((float4*)(sp_s + c_local * 32))[f4] = spo;
        }
        __syncthreads();

        // partial first-layer hidden over this split's 64 channels
        const int hw_l = tid & 31;
        const int rg   = tid >> 5;
        const int r0   = rg * 2, r1 = r0 + 1;
        float a0 = 0.f, a1 = 0.f;
#pragma unroll 8
        for (int cl = 0; cl < 64; cl++) {
            const float v = sp_s[cl * 32 + hw_l];
            a0 = fmaf(w1s[r0 * 64 + cl], v, a0);
            a1 = fmaf(w1s[r1 * 64 + cl], v, a1);
        }
        float* hp = g_hid_part + (size_t)((q * BB + b) * CR) * HWN + tile * 32 + hw_l;
        hp[(size_t)r0 * HWN] = a0;
        hp[(size_t)r1 * HWN] = a1;

        // tp partials out (layout [b][t][tile][c], coalesced in c)
#pragma unroll
        for (int i = 0; i < 4; i++) {
            const int e  = tid + i * 256;
            const int t  = e >> 6;
            const int cl = e & 63;
            g_tpp[(size_t)((b * TT + t) * 32 + tile) * CC + q * 64 + cl] = tp_s[t * 64 + cl];
        }
        if (tid < 64) {
            float s = 0.f;
#pragma unroll
            for (int t = 0; t < TT; t++) s += tp_s[t * 64 + tid];
            g_cpp[(size_t)(b * 32 + tile) * CC + q * 64 + tid] = s;
        }
    }
    grid_barrier();

    // ===== Phase B: SE (bid<128, extra job) + spatial att (every CTA) ========
    if (bid < 128) {
        // ---- temporal + channel SE -> g_comb ----
        const int b = bid >> 4;
        const int t = bid & 15;
        float* pt   = sm;         // [256]
        float* pc   = sm + 256;   // [256]
        float* hids = sm + 512;   // [32]

        {
            float s = 0.f;
            const float* base = g_tpp + (size_t)(b * TT + t) * 32 * CC + tid;
#pragma unroll 8
            for (int tile = 0; tile < 32; tile++) s += __ldcg(base + tile * CC);
            pt[tid] = s * (1.f / HWN);

            float s2 = 0.f;
            const float* base2 = g_cpp + (size_t)b * 32 * CC + tid;
#pragma unroll 8
            for (int tile = 0; tile < 32; tile++) s2 += __ldcg(base2 + tile * CC);
            pc[tid] = s2 * (1.f / (TT * HWN));
        }
        __syncthreads();

        if (tid < CR) {
            float s = bt1[tid];
            for (int c = 0; c < CC; c++) s = fmaf(wt1[tid * CC + c], pt[c], s);
            hids[tid] = fmaxf(s, 0.f);
        } else if (tid < 2 * CR) {
            const int r = tid - CR;
            float s = bc1[r];
            for (int c = 0; c < CC; c++) s = fmaf(wc1[r * CC + c], pc[c], s);
            hids[tid] = fmaxf(s, 0.f);
        }
        __syncthreads();

        float at = bt2[tid];
        float ac = bc2[tid];
#pragma unroll
        for (int r = 0; r < CR; r++) {
            at = fmaf(wt2[tid * CR + r], hids[r],      at);
            ac = fmaf(wc2[tid * CR + r], hids[CR + r], ac);
        }
        g_comb[(b * CC + tid) * TT + t] = sigmoidf(at) * sigmoidf(ac);
        __syncthreads();
    }

    {
        // ---- spatial att: job = (b, 8-hw window); all 1024 CTAs ----
        const int b   = bid >> 7;
        const int hw0 = (bid & 127) * 8;
        float* hidf = sm + 1024;   // [r][hwl] 128 floats (clear of SE regions)

        if (tid < CR * 8) {
            const int r  = tid >> 3;
            const int hl = tid & 7;
            float s = bs1[r];
#pragma unroll
            for (int q = 0; q < 4; q++)
                s += __ldcg(&g_hid_part[(size_t)((q * BB + b) * CR + r) * HWN + hw0 + hl]);
            hidf[r * 8 + hl] = fmaxf(s, 0.f);
        }
        __syncthreads();

        const int c8  = tid >> 3;   // 0..31
        const int hwl = tid & 7;    // 0..7
        float* attb = g_att + (size_t)(b * CC) * HWN + hw0 + hwl;

#pragma unroll
        for (int i = 0; i < 8; i++) {
            const int c = c8 * 8 + i;
            const float4* wr = (const float4*)(ws2 + c * CR);
            float a = __ldg(&bs2[c]);
            {
                const float4 w0 = __ldg(wr + 0);
                a = fmaf(w0.x, hidf[0 * 8 + hwl], a);
                a = fmaf(w0.y, hidf[1 * 8 + hwl], a);
                a = fmaf(w0.z, hidf[2 * 8 + hwl], a);
                a = fmaf(w0.w, hidf[3 * 8 + hwl], a);
            }
            {
                const float4 w1 = __ldg(wr + 1);
                a = fmaf(w1.x, hidf[4 * 8 + hwl], a);
                a = fmaf(w1.y, hidf[5 * 8 + hwl], a);
                a = fmaf(w1.z, hidf[6 * 8 + hwl], a);
                a = fmaf(w1.w, hidf[7 * 8 + hwl], a);
            }
            {
                const float4 w2 = __ldg(wr + 2);
                a = fmaf(w2.x, hidf[8 * 8 + hwl],  a);
                a = fmaf(w2.y, hidf[9 * 8 + hwl],  a);
                a = fmaf(w2.z, hidf[10 * 8 + hwl], a);
                a = fmaf(w2.w, hidf[11 * 8 + hwl], a);
            }
            {
                const float4 w3 = __ldg(wr + 3);
                a = fmaf(w3.x, hidf[12 * 8 + hwl], a);
                a = fmaf(w3.y, hidf[13 * 8 + hwl], a);
                a = fmaf(w3.z, hidf[14 * 8 + hwl], a);
                a = fmaf(w3.w, hidf[15 * 8 + hwl], a);
            }
            attb[(size_t)c * HWN] = sigmoidf(a);
        }
    }
    grid_barrier();

    // ===== Phase C: streaming apply (2048 jobs, 2 per CTA) ===================
    {
        float* smc = sm;   // [16]
        for (int j = bid; j < 2048; j += G) {
            if (tid < TT) smc[tid] = __ldcg(&g_comb[j * TT + tid]);
            __syncthreads();

            const float4 a = __ldcg(((const float4*)(g_att + (size_t)j * HWN)) + tid);
            const float4* xp = (const float4*)(x + (size_t)j * (TT * HWN));
            float4* op       = (float4*)(out + (size_t)j * (TT * HWN));
#pragma unroll
            for (int t = 0; t < TT; t++) {
                const float s = smc[t];
                float4 v = xp[t * (HWN / 4) + tid];
                v.x = v.x * a.x * s;
                v.y = v.y * a.y * s;
                v.z = v.z * a.z * s;
                v.w = v.w * a.w * s;
                op[t * (HWN / 4) + tid] = v;
            }
            __syncthreads();
        }
    }
}

// ---------------- launch -----------------------------------------------------
extern "C" void kernel_launch(void* const* d_in, const int* in_sizes, int n_in,
                              void* d_out, int out_size) {
    const float* x   = (const float*)d_in[0];
    const float* ws1 = (const float*)d_in[1];
    const float* bs1 = (const float*)d_in[2];
    const float* ws2 = (const float*)d_in[3];
    const float* bs2 = (const float*)d_in[4];
    const float* wt1 = (const float*)d_in[5];
    const float* bt1 = (const float*)d_in[6];
    const float* wt2 = (const float*)d_in[7];
    const float* bt2 = (const float*)d_in[8];
    const float* wc1 = (const float*)d_in[9];
    const float* bc1 = (const float*)d_in[10];
    const float* wc2 = (const float*)d_in[11];
    const float* bc2 = (const float*)d_in[12];
    float* out = (float*)d_out;

    fused_kernel<<<G, 256>>>(x, ws1, bs1, ws2, bs2,
                             wt1, bt1, wt2, bt2,
                             wc1, bc1, wc2, bc2, out);
}